// round 13
// baseline (speedup 1.0000x reference)
#include <cuda_runtime.h>
#include <cuda_fp16.h>
#include <cstdint>
#include <math.h>

// LSTM cell B=4096, I=1024, H=1024 — single-pass fp16 HMMA (mma.sync), fp32 accum.
// R13 = R12 GEMM core (128x128 CTA tile, 256 thr / 8 warps, 2 CTAs/SM, warp tile
// 64x32, BK=64, 3-stage cp.async) with the B operand switched to row-major [k][n]
// smem tiles loaded via ldmatrix.x4.TRANS — so conv W becomes a pure streaming
// fp32->fp16 convert (no transpose smem round-trip).
// B smem: 64 k-rows x 128 gate-blocked cols (c = g*32 + jj), 256B rows,
// XOR-(k&7) 16B-unit swizzle. Warp wn owns gate wn.

#define MDIM 4096
#define HDIM 1024
#define KD   2048
#define BM   128
#define BN   128
#define TNJ  32
#define BK   64
#define NCHUNK 32                   // 2048 / 64
#define STAGES 3
#define STAGE_BYTES 32768           // A 128x128B + B 64x256B
#define STAGE_B_OFF 16384
#define SMEM_TOTAL (STAGES * STAGE_BYTES)   // 98304

// fp16 scratch (32 MB): A [m][k], W row-major [k][4096] (NO transpose)
__device__ __align__(16) __half g_Ah[(size_t)MDIM * KD];
__device__ __align__(16) __half g_Wh[(size_t)KD * 4096];

__device__ __forceinline__ uint32_t smem_u32(const void* p) {
    uint32_t a;
    asm("{ .reg .u64 t; cvta.to.shared.u64 t, %1; cvt.u32.u64 %0, t; }" : "=r"(a) : "l"(p));
    return a;
}
__device__ __forceinline__ void cp_async16(uint32_t dst, const void* src) {
    asm volatile("cp.async.cg.shared.global [%0], [%1], 16;" :: "r"(dst), "l"(src));
}
#define CP_COMMIT() asm volatile("cp.async.commit_group;" ::: "memory")
#define CP_WAIT1()  asm volatile("cp.async.wait_group 1;" ::: "memory")

__device__ __forceinline__ void ldsm_x4(uint32_t r[4], uint32_t addr) {
    asm volatile("ldmatrix.sync.aligned.m8n8.x4.shared.b16 {%0,%1,%2,%3}, [%4];"
                 : "=r"(r[0]), "=r"(r[1]), "=r"(r[2]), "=r"(r[3]) : "r"(addr));
}
__device__ __forceinline__ void ldsm_x4_trans(uint32_t r[4], uint32_t addr) {
    asm volatile("ldmatrix.sync.aligned.m8n8.x4.trans.shared.b16 {%0,%1,%2,%3}, [%4];"
                 : "=r"(r[0]), "=r"(r[1]), "=r"(r[2]), "=r"(r[3]) : "r"(addr));
}
__device__ __forceinline__ void mma_fp16(float d[4], const uint32_t a[4],
                                         uint32_t b0, uint32_t b1) {
    asm volatile(
        "mma.sync.aligned.m16n8k16.row.col.f32.f16.f16.f32 "
        "{%0,%1,%2,%3}, {%4,%5,%6,%7}, {%8,%9}, {%0,%1,%2,%3};"
        : "+f"(d[0]), "+f"(d[1]), "+f"(d[2]), "+f"(d[3])
        : "r"(a[0]), "r"(a[1]), "r"(a[2]), "r"(a[3]), "r"(b0), "r"(b1));
}

__device__ __forceinline__ float fast_sigmoid(float x) {
    return 1.0f / (1.0f + __expf(-x));
}
__device__ __forceinline__ float fast_tanh(float x) {
    return 1.0f - 2.0f / (__expf(2.0f * x) + 1.0f);   // exact saturation at +-inf
}

// ---------------- conversion kernel: two pure streaming converts ----------------
// blocks [0, 2048): A path  — thread: 16 consecutive k of one m-row (4x LDG.128)
// blocks [2048, 4096): W path — thread: 16 consecutive n of one k-row (4x LDG.128)
__global__ void conv_fused_kernel(const float* __restrict__ x,
                                  const float* __restrict__ h,
                                  const float* __restrict__ w_i,
                                  const float* __restrict__ w_h)
{
    if (blockIdx.x < 2048) {
        size_t q = (size_t)blockIdx.x * 256 + threadIdx.x;
        int m  = (int)(q >> 7);              // 128 threads per m-row
        int k0 = ((int)q & 127) << 4;        // within one source half
        const float* src = (k0 < 1024) ? (x + (size_t)m * 1024 + k0)
                                       : (h + (size_t)m * 1024 + (k0 - 1024));
        float4 v[4];
        #pragma unroll
        for (int i = 0; i < 4; ++i)
            v[i] = *reinterpret_cast<const float4*>(src + i * 4);
        size_t o = (size_t)m * KD + k0;
        #pragma unroll
        for (int i = 0; i < 4; ++i) {
            *reinterpret_cast<__half2*>(&g_Ah[o + i * 4])     = __floats2half2_rn(v[i].x, v[i].y);
            *reinterpret_cast<__half2*>(&g_Ah[o + i * 4 + 2]) = __floats2half2_rn(v[i].z, v[i].w);
        }
    } else {
        size_t q = (size_t)(blockIdx.x - 2048) * 256 + threadIdx.x;
        int k  = (int)(q >> 8);              // 256 threads per k-row
        int n0 = ((int)q & 255) << 4;
        const float* src = (k < 1024) ? (w_i + (size_t)k * 4096 + n0)
                                      : (w_h + (size_t)(k - 1024) * 4096 + n0);
        float4 v[4];
        #pragma unroll
        for (int i = 0; i < 4; ++i)
            v[i] = *reinterpret_cast<const float4*>(src + i * 4);
        size_t o = (size_t)k * 4096 + n0;
        #pragma unroll
        for (int i = 0; i < 4; ++i) {
            *reinterpret_cast<__half2*>(&g_Wh[o + i * 4])     = __floats2half2_rn(v[i].x, v[i].y);
            *reinterpret_cast<__half2*>(&g_Wh[o + i * 4 + 2]) = __floats2half2_rn(v[i].z, v[i].w);
        }
    }
}

// ---------------- main GEMM + LSTM kernel ----------------
__global__ __launch_bounds__(256, 2)
void lstm_hmma_kernel(const float* __restrict__ c_t,
                      const float* __restrict__ b_i,
                      const float* __restrict__ b_h,
                      float* __restrict__ out)
{
    extern __shared__ __align__(1024) char dsm[];
    const uint32_t sb = smem_u32(dsm);
    const int tid = threadIdx.x;
    const int wid = tid >> 5;
    const int lid = tid & 31;
    const int mbase = blockIdx.y * BM;
    const int nbase = blockIdx.x * TNJ;

    const int wm = wid & 1;    // 2 row-groups of 64
    const int wn = wid >> 1;   // 4 col-groups of 32 (= gate wn)

    // A ldmatrix offsets (128B rows, XOR ks*32 per k-step) — unchanged
    uint32_t pa[4];
    #pragma unroll
    for (int i = 0; i < 4; ++i) {
        int row = wm * 64 + i * 16 + (lid & 15);
        int sub = ((lid >> 4) & 1) * 16;
        pa[i] = row * 128 + (sub ^ ((row & 7) << 4));
    }
    // B ldmatrix.trans offsets: tile [64 k][128 c] fp16, 256B rows,
    // 16B-unit swizzle: unit' = c4 ^ (k&7). Lane group g=lid>>3 -> tile
    // (strip jh*2 + (g>>1), ktile g&1); lane l=lid&7 -> k-row l (k&7 == l).
    // kstep advance = +ks*4096 bytes.
    uint32_t pbT[2];
    {
        const int group = lid >> 3, l = lid & 7;
        #pragma unroll
        for (int jh = 0; jh < 2; ++jh) {
            int s  = jh * 2 + (group >> 1);
            int c4 = wn * 4 + s;
            pbT[jh] = STAGE_B_OFF + ((group & 1) * 8 + l) * 256 + ((c4 ^ l) << 4);
        }
    }

    float acc[4][4][4];
    #pragma unroll
    for (int i = 0; i < 4; ++i)
        #pragma unroll
        for (int j = 0; j < 4; ++j)
            #pragma unroll
            for (int c = 0; c < 4; ++c) acc[i][j][c] = 0.0f;

    auto load_stage = [&](int t) {
        const int koff = t * BK;
        const uint32_t abase = sb + (t % STAGES) * STAGE_BYTES;
        const uint32_t bbase = abase + STAGE_B_OFF;
        #pragma unroll
        for (int q = 0; q < 4; ++q) {            // A: 128 rows x 8 chunks / 256 thr
            int l = q * 256 + tid;
            int row = l >> 3, ck = l & 7;
            uint32_t boff = ck * 16;
            cp_async16(abase + row * 128 + (boff ^ ((row & 7) << 4)),
                       g_Ah + (size_t)(mbase + row) * KD + koff + ck * 8);
        }
        #pragma unroll
        for (int q = 0; q < 4; ++q) {            // B: 64 k-rows x 16 units / 256 thr
            int l = q * 256 + tid;
            int r = l >> 4, c4 = l & 15;
            cp_async16(bbase + r * 256 + ((c4 ^ (r & 7)) << 4),
                       g_Wh + (size_t)(koff + r) * 4096 +
                           ((c4 >> 2) << 10) + nbase + ((c4 & 3) << 3));
        }
    };

    load_stage(0); CP_COMMIT();
    load_stage(1); CP_COMMIT();

    for (int t = 0; t < NCHUNK; ++t) {
        CP_WAIT1();
        __syncthreads();
        if (t + 2 < NCHUNK) load_stage(t + 2);
        CP_COMMIT();

        const uint32_t sbase = sb + (t % STAGES) * STAGE_BYTES;
        #pragma unroll
        for (int ks = 0; ks < 4; ++ks) {
            uint32_t a[4][4], b[2][4];
            #pragma unroll
            for (int jh = 0; jh < 2; ++jh)
                ldsm_x4_trans(b[jh], sbase + pbT[jh] + ks * 4096);
            const uint32_t k0b = ks * 32;
            #pragma unroll
            for (int i = 0; i < 4; ++i) ldsm_x4(a[i], sbase + (pa[i] ^ k0b));
            #pragma unroll
            for (int i = 0; i < 4; ++i) {
                mma_fp16(acc[i][0], a[i], b[0][0], b[0][1]);
                mma_fp16(acc[i][1], a[i], b[0][2], b[0][3]);
                mma_fp16(acc[i][2], a[i], b[1][0], b[1][1]);
                mma_fp16(acc[i][3], a[i], b[1][2], b[1][3]);
            }
        }
    }

    // ---- epilogue: hoist independent global loads BEFORE the staging barrier ----
    const int jj = tid & 31;
    const int rg = tid >> 5;            // 0..7, 16 rows each
    const int nb = nbase + jj;

    float bias_v[4];
    #pragma unroll
    for (int g = 0; g < 4; ++g)
        bias_v[g] = b_i[g * 1024 + nb] + b_h[g * 1024 + nb];

    float cold[16];
    #pragma unroll
    for (int rr = 0; rr < 16; ++rr)
        cold[rr] = c_t[(size_t)(mbase + rg * 16 + rr) * HDIM + nb];

    // stage ifgo tile (cols = g*32 + jj) to smem, reuse pipeline smem
    __syncthreads();
    float* tile = reinterpret_cast<float*>(dsm);   // [128][132] floats
    const int trow0 = wm * 64 + (lid >> 2);
    const int tcol0 = wn * 32 + (lid & 3) * 2;
    #pragma unroll
    for (int i = 0; i < 4; ++i)
        #pragma unroll
        for (int j = 0; j < 4; ++j) {
            int r0 = trow0 + i * 16;
            int cc = tcol0 + j * 8;
            *reinterpret_cast<float2*>(&tile[r0 * 132 + cc]) =
                make_float2(acc[i][j][0], acc[i][j][1]);
            *reinterpret_cast<float2*>(&tile[(r0 + 8) * 132 + cc]) =
                make_float2(acc[i][j][2], acc[i][j][3]);
        }
    __syncthreads();

    float* out_h = out;
    float* out_c = out + (size_t)MDIM * HDIM;
    #pragma unroll
    for (int rr = 0; rr < 16; ++rr) {
        int row  = rg * 16 + rr;
        int grow = mbase + row;
        const float* trow = &tile[row * 132];
        float iv = fast_sigmoid(trow[jj]      + bias_v[0]);
        float fv = fast_sigmoid(trow[32 + jj] + bias_v[1]);
        float gv = fast_tanh   (trow[64 + jj] + bias_v[2]);
        float ov = fast_sigmoid(trow[96 + jj] + bias_v[3]);
        float c2 = fmaf(fv, cold[rr], iv * gv);
        out_c[(size_t)grow * HDIM + nb] = c2;
        out_h[(size_t)grow * HDIM + nb] = ov * fast_tanh(c2);
    }
}

extern "C" void kernel_launch(void* const* d_in, const int* in_sizes, int n_in,
                              void* d_out, int out_size)
{
    const float* x   = (const float*)d_in[0];
    const float* h_t = (const float*)d_in[1];
    const float* c_t = (const float*)d_in[2];
    const float* w_i = (const float*)d_in[3];
    const float* w_h = (const float*)d_in[4];
    const float* b_i = (const float*)d_in[5];
    const float* b_h = (const float*)d_in[6];
    float* out = (float*)d_out;

    static bool attr_set = false;
    if (!attr_set) {
        cudaFuncSetAttribute(lstm_hmma_kernel,
                             cudaFuncAttributeMaxDynamicSharedMemorySize, SMEM_TOTAL);
        attr_set = true;
    }

    conv_fused_kernel<<<4096, 256>>>(x, h_t, w_i, w_h);
    lstm_hmma_kernel<<<dim3(HDIM / TNJ, MDIM / BM), 256, SMEM_TOTAL>>>(c_t, b_i, b_h, out);
}

// round 14
// speedup vs baseline: 1.0410x; 1.0410x over previous
#include <cuda_runtime.h>
#include <cuda_fp16.h>
#include <cstdint>
#include <math.h>

// LSTM cell B=4096, I=1024, H=1024 — single-pass fp16 HMMA (mma.sync), fp32 accum.
// R14 = R12 (best: 192.9us) with ONE mainloop change: after the per-chunk
// barrier, issue kstep-0 LDSM+MMA BEFORE the next stage's cp.async batch, so the
// post-barrier critical path starts with tensor work instead of ~8 LDGSTS+addr math.
// Core: 128x128 CTA tile, 256 thr / 8 warps, 2 CTAs/SM, warp tile 64x32,
// BK=64, 3-stage cp.async, W transposed [n][k], gate-interleaved N (n=jj*4+g).

#define MDIM 4096
#define HDIM 1024
#define KD   2048
#define BM   128
#define BN   128
#define TNJ  32
#define BK   64
#define NCHUNK 32                   // 2048 / 64
#define STAGES 3
#define STAGE_BYTES 32768           // A 128x128B + B 128x128B
#define STAGE_B_OFF 16384
#define SMEM_TOTAL (STAGES * STAGE_BYTES)   // 98304

// fp16 scratch (32 MB), device globals (sanctioned scratch workaround)
__device__ __align__(16) __half g_Ah[(size_t)MDIM * KD];
__device__ __align__(16) __half g_Wh[(size_t)4096 * KD];   // transposed [n][k]

__device__ __forceinline__ uint32_t smem_u32(const void* p) {
    uint32_t a;
    asm("{ .reg .u64 t; cvta.to.shared.u64 t, %1; cvt.u32.u64 %0, t; }" : "=r"(a) : "l"(p));
    return a;
}
__device__ __forceinline__ void cp_async16(uint32_t dst, const void* src) {
    asm volatile("cp.async.cg.shared.global [%0], [%1], 16;" :: "r"(dst), "l"(src));
}
#define CP_COMMIT() asm volatile("cp.async.commit_group;" ::: "memory")
#define CP_WAIT1()  asm volatile("cp.async.wait_group 1;" ::: "memory")

__device__ __forceinline__ void ldsm_x4(uint32_t r[4], uint32_t addr) {
    asm volatile("ldmatrix.sync.aligned.m8n8.x4.shared.b16 {%0,%1,%2,%3}, [%4];"
                 : "=r"(r[0]), "=r"(r[1]), "=r"(r[2]), "=r"(r[3]) : "r"(addr));
}
__device__ __forceinline__ void mma_fp16(float d[4], const uint32_t a[4],
                                         uint32_t b0, uint32_t b1) {
    asm volatile(
        "mma.sync.aligned.m16n8k16.row.col.f32.f16.f16.f32 "
        "{%0,%1,%2,%3}, {%4,%5,%6,%7}, {%8,%9}, {%0,%1,%2,%3};"
        : "+f"(d[0]), "+f"(d[1]), "+f"(d[2]), "+f"(d[3])
        : "r"(a[0]), "r"(a[1]), "r"(a[2]), "r"(a[3]), "r"(b0), "r"(b1));
}

__device__ __forceinline__ float fast_sigmoid(float x) {
    return 1.0f / (1.0f + __expf(-x));
}
__device__ __forceinline__ float fast_tanh(float x) {
    return 1.0f - 2.0f / (__expf(2.0f * x) + 1.0f);   // exact saturation at +-inf
}

// ---------------- conversion kernel ----------------
// blocks [0, 2048): A path — thread handles 16 consecutive k (4 x LDG.128, MLP 4)
// blocks [2048, 6144): W path — 64(k) x 32(n) transpose tile, half2 stores
__global__ void conv_fused_kernel(const float* __restrict__ x,
                                  const float* __restrict__ h,
                                  const float* __restrict__ w_i,
                                  const float* __restrict__ w_h)
{
    if (blockIdx.x < 2048) {
        size_t q = (size_t)blockIdx.x * 256 + threadIdx.x;
        int m  = (int)(q >> 7);              // 128 threads per m-row
        int k0 = ((int)q & 127) << 4;        // within one source half
        const float* src = (k0 < 1024) ? (x + (size_t)m * 1024 + k0)
                                       : (h + (size_t)m * 1024 + (k0 - 1024));
        float4 v[4];
        #pragma unroll
        for (int i = 0; i < 4; ++i)
            v[i] = *reinterpret_cast<const float4*>(src + i * 4);
        size_t o = (size_t)m * KD + k0;
        #pragma unroll
        for (int i = 0; i < 4; ++i) {
            *reinterpret_cast<__half2*>(&g_Ah[o + i * 4])     = __floats2half2_rn(v[i].x, v[i].y);
            *reinterpret_cast<__half2*>(&g_Ah[o + i * 4 + 2]) = __floats2half2_rn(v[i].z, v[i].w);
        }
    } else {
        // 4096 blocks: 32 k-tiles (of 64) x 128 n-tiles (of 32)
        __shared__ float tile[64][33];
        int bw = blockIdx.x - 2048;
        int tx = threadIdx.x & 31, ty = threadIdx.x >> 5;   // 32 x 8
        int k0 = (bw & 31) * 64, n0 = (bw >> 5) * 32;
        #pragma unroll
        for (int j = 0; j < 8; ++j) {                       // 8 batched loads
            int k = k0 + ty + j * 8;
            const float* src = (k < 1024) ? (w_i + (size_t)k * 4096)
                                          : (w_h + (size_t)(k - 1024) * 4096);
            tile[ty + j * 8][tx] = src[n0 + tx];
        }
        __syncthreads();
        // transpose-store: for fixed n (ty, j), tx sweeps kk = k0 + 2*tx over all
        // 64 k-values. 32 n x 32 pair-slots = full tile.
        #pragma unroll
        for (int j = 0; j < 4; ++j) {
            int n = n0 + ty + j * 8;
            __half2 hv = __floats2half2_rn(tile[2 * tx][ty + j * 8],
                                           tile[2 * tx + 1][ty + j * 8]);
            *reinterpret_cast<__half2*>(&g_Wh[(size_t)n * KD + k0 + 2 * tx]) = hv;
        }
    }
}

// ---------------- main GEMM + LSTM kernel ----------------
__global__ __launch_bounds__(256, 2)
void lstm_hmma_kernel(const float* __restrict__ c_t,
                      const float* __restrict__ b_i,
                      const float* __restrict__ b_h,
                      float* __restrict__ out)
{
    extern __shared__ __align__(1024) char dsm[];
    const uint32_t sb = smem_u32(dsm);
    const int tid = threadIdx.x;
    const int wid = tid >> 5;
    const int lid = tid & 31;
    const int mbase = blockIdx.y * BM;
    const int nbase = blockIdx.x * TNJ;

    const int wm = wid & 1;    // 2 row-groups of 64
    const int wn = wid >> 1;   // 4 col-groups of 32

    // ldmatrix per-thread stage-relative offsets (XOR with ks*32 per k-step)
    uint32_t pa[4], pb[2];
    #pragma unroll
    for (int i = 0; i < 4; ++i) {
        int row = wm * 64 + i * 16 + (lid & 15);
        int sub = ((lid >> 4) & 1) * 16;
        pa[i] = row * 128 + (sub ^ ((row & 7) << 4));
    }
    #pragma unroll
    for (int jh = 0; jh < 2; ++jh) {
        int row = wn * 32 + jh * 16 + ((lid >> 4) << 3) + (lid & 7);
        int sub = ((lid >> 3) & 1) * 16;
        pb[jh] = STAGE_B_OFF + row * 128 + (sub ^ ((row & 7) << 4));
    }

    float acc[4][4][4];
    #pragma unroll
    for (int i = 0; i < 4; ++i)
        #pragma unroll
        for (int j = 0; j < 4; ++j)
            #pragma unroll
            for (int c = 0; c < 4; ++c) acc[i][j][c] = 0.0f;

    auto load_stage = [&](int t) {
        const int koff = t * BK;
        const uint32_t abase = sb + (t % STAGES) * STAGE_BYTES;
        const uint32_t bbase = abase + STAGE_B_OFF;
        #pragma unroll
        for (int q = 0; q < 4; ++q) {            // A: 128 rows x 8 chunks / 256 thr
            int l = q * 256 + tid;
            int row = l >> 3, ck = l & 7;
            uint32_t boff = ck * 16;
            cp_async16(abase + row * 128 + (boff ^ ((row & 7) << 4)),
                       g_Ah + (size_t)(mbase + row) * KD + koff + ck * 8);
        }
        #pragma unroll
        for (int q = 0; q < 4; ++q) {            // B: 128 rows x 8 chunks / 256 thr
            int l = q * 256 + tid;
            int r = l >> 3, ck = l & 7;
            int n = ((r & 3) << 10) + nbase + (r >> 2);   // n = g*1024 + nbase + jj
            uint32_t boff = ck * 16;
            cp_async16(bbase + r * 128 + (boff ^ ((r & 7) << 4)),
                       g_Wh + (size_t)n * KD + koff + ck * 8);
        }
    };

    load_stage(0); CP_COMMIT();
    load_stage(1); CP_COMMIT();

    for (int t = 0; t < NCHUNK; ++t) {
        CP_WAIT1();
        __syncthreads();

        const uint32_t sbase = sb + (t % STAGES) * STAGE_BYTES;

        // ---- kstep 0 first: tensor work starts immediately after the barrier ----
        {
            uint32_t a[4][4], b[2][4];
            #pragma unroll
            for (int jh = 0; jh < 2; ++jh) ldsm_x4(b[jh], sbase + pb[jh]);
            #pragma unroll
            for (int i = 0; i < 4; ++i) ldsm_x4(a[i], sbase + pa[i]);
            #pragma unroll
            for (int i = 0; i < 4; ++i) {
                mma_fp16(acc[i][0], a[i], b[0][0], b[0][1]);
                mma_fp16(acc[i][1], a[i], b[0][2], b[0][3]);
                mma_fp16(acc[i][2], a[i], b[1][0], b[1][1]);
                mma_fp16(acc[i][3], a[i], b[1][2], b[1][3]);
            }
        }

        // ---- prefetch stage t+2 (overlaps with ks0 MMA execution) ----
        if (t + 2 < NCHUNK) load_stage(t + 2);
        CP_COMMIT();

        // ---- ksteps 1..3 ----
        #pragma unroll
        for (int ks = 1; ks < 4; ++ks) {
            const uint32_t k0b = ks * 32;
            uint32_t a[4][4], b[2][4];
            #pragma unroll
            for (int jh = 0; jh < 2; ++jh) ldsm_x4(b[jh], sbase + (pb[jh] ^ k0b));
            #pragma unroll
            for (int i = 0; i < 4; ++i) ldsm_x4(a[i], sbase + (pa[i] ^ k0b));
            #pragma unroll
            for (int i = 0; i < 4; ++i) {
                mma_fp16(acc[i][0], a[i], b[0][0], b[0][1]);
                mma_fp16(acc[i][1], a[i], b[0][2], b[0][3]);
                mma_fp16(acc[i][2], a[i], b[1][0], b[1][1]);
                mma_fp16(acc[i][3], a[i], b[1][2], b[1][3]);
            }
        }
    }

    // ---- epilogue: hoist independent global loads BEFORE the staging barrier ----
    const int jj = tid & 31;
    const int rg = tid >> 5;            // 0..7, 16 rows each
    const int nb = nbase + jj;

    float bias_v[4];
    #pragma unroll
    for (int g = 0; g < 4; ++g)
        bias_v[g] = b_i[g * 1024 + nb] + b_h[g * 1024 + nb];

    float cold[16];
    #pragma unroll
    for (int rr = 0; rr < 16; ++rr)
        cold[rr] = c_t[(size_t)(mbase + rg * 16 + rr) * HDIM + nb];

    // stage ifgo tile to smem (reuse pipeline smem)
    __syncthreads();
    float* tile = reinterpret_cast<float*>(dsm);   // [128][132] floats
    const int trow0 = wm * 64 + (lid >> 2);
    const int tcol0 = wn * 32 + (lid & 3) * 2;
    #pragma unroll
    for (int i = 0; i < 4; ++i)
        #pragma unroll
        for (int j = 0; j < 4; ++j) {
            int r0 = trow0 + i * 16;
            int cc = tcol0 + j * 8;
            *reinterpret_cast<float2*>(&tile[r0 * 132 + cc]) =
                make_float2(acc[i][j][0], acc[i][j][1]);
            *reinterpret_cast<float2*>(&tile[(r0 + 8) * 132 + cc]) =
                make_float2(acc[i][j][2], acc[i][j][3]);
        }
    __syncthreads();

    float* out_h = out;
    float* out_c = out + (size_t)MDIM * HDIM;
    #pragma unroll
    for (int rr = 0; rr < 16; ++rr) {
        int row  = rg * 16 + rr;
        int grow = mbase + row;
        float4 v = *reinterpret_cast<const float4*>(&tile[row * 132 + jj * 4]);
        float iv = fast_sigmoid(v.x + bias_v[0]);
        float fv = fast_sigmoid(v.y + bias_v[1]);
        float gv = fast_tanh(v.z + bias_v[2]);
        float ov = fast_sigmoid(v.w + bias_v[3]);
        float c2 = fmaf(fv, cold[rr], iv * gv);
        out_c[(size_t)grow * HDIM + nb] = c2;
        out_h[(size_t)grow * HDIM + nb] = ov * fast_tanh(c2);
    }
}

extern "C" void kernel_launch(void* const* d_in, const int* in_sizes, int n_in,
                              void* d_out, int out_size)
{
    const float* x   = (const float*)d_in[0];
    const float* h_t = (const float*)d_in[1];
    const float* c_t = (const float*)d_in[2];
    const float* w_i = (const float*)d_in[3];
    const float* w_h = (const float*)d_in[4];
    const float* b_i = (const float*)d_in[5];
    const float* b_h = (const float*)d_in[6];
    float* out = (float*)d_out;

    static bool attr_set = false;
    if (!attr_set) {
        cudaFuncSetAttribute(lstm_hmma_kernel,
                             cudaFuncAttributeMaxDynamicSharedMemorySize, SMEM_TOTAL);
        attr_set = true;
    }

    conv_fused_kernel<<<6144, 256>>>(x, h_t, w_i, w_h);
    lstm_hmma_kernel<<<dim3(HDIM / TNJ, MDIM / BM), 256, SMEM_TOTAL>>>(c_t, b_i, b_h, out);
}